// round 14
// baseline (speedup 1.0000x reference)
#include <cuda_runtime.h>
#include <cuda_bf16.h>
#include <math.h>
#include <stdint.h>

#define NN 4096
#define MEM 512
#define HS 4224   // padded row count for h_split (level tiles read past last node)

constexpr int NSPLIT = 4;                     // max split-K factor for level GEMMs
constexpr size_t IOU_P = (size_t)683 * 1536;  // iou partial slice stride
constexpr size_t FW_P  = (size_t)(NN + 1) * MEM;  // fw partial slice stride

// ---------------- scratch (static device globals; no allocation) ----------------
__device__ float g_ifou[NN * 2048];
__device__ float g_c[(NN + 1) * MEM];
__device__ float g_h[(NN + 1) * MEM];
__device__ float g_iou[NSPLIT * 683 * 1536];        // split-K partials
__device__ float g_fw[NSPLIT * (NN + 1) * MEM];     // split-K partials (sentinel rows stay 0)
// pre-split (hi,mid) bf16x2 pairs, packed per k-pair
__device__ uint2 g_wxs[256 * 2048];   // Wx split [kp][n]
__device__ uint2 g_wss[256 * 1536];   // Ws split [kp][n]
__device__ uint2 g_wfs[256 * 512];    // Wf split [kp][n]
__device__ uint2 g_isp[256 * 4096];   // inputs split, transposed [kp][row]
__device__ uint2 g_hsp[256 * HS];     // h split, transposed [kp][node]
// grid barrier state
__device__ unsigned g_bar_cnt = 0;
__device__ unsigned g_bar_gen = 0;

__device__ __forceinline__ float sigmoidf_(float x) { return 1.0f / (1.0f + expf(-x)); }

__device__ __forceinline__ int child_id(int p, int k) {
    int c = 4 * p - 12289 + k;
    return c < 0 ? NN : c;
}

// ---------------- bf16 split helpers ----------------
__device__ __forceinline__ uint2 split_pack(float x0, float x1) {
    __nv_bfloat162 h = __floats2bfloat162_rn(x0, x1);
    float r0 = x0 - __bfloat162float(h.x);
    float r1 = x1 - __bfloat162float(h.y);
    __nv_bfloat162 m = __floats2bfloat162_rn(r0, r1);
    uint2 o;
    o.x = *reinterpret_cast<uint32_t*>(&h);
    o.y = *reinterpret_cast<uint32_t*>(&m);
    return o;
}

__device__ __forceinline__ void mma16(float* d, const uint32_t* a, const uint32_t* b) {
    asm volatile(
        "mma.sync.aligned.m16n8k16.row.col.f32.bf16.bf16.f32 "
        "{%0,%1,%2,%3}, {%4,%5,%6,%7}, {%8,%9}, {%0,%1,%2,%3};"
        : "+f"(d[0]), "+f"(d[1]), "+f"(d[2]), "+f"(d[3])
        : "r"(a[0]), "r"(a[1]), "r"(a[2]), "r"(a[3]), "r"(b[0]), "r"(b[1]));
}

__device__ __forceinline__ void cpa8(uint32_t dst, const void* src) {
    asm volatile("cp.async.ca.shared.global [%0], [%1], 8;" :: "r"(dst), "l"(src));
}
__device__ __forceinline__ void cpa16(uint32_t dst, const void* src) {
    asm volatile("cp.async.cg.shared.global [%0], [%1], 16;" :: "r"(dst), "l"(src));
}
__device__ __forceinline__ void cpa_commit() {
    asm volatile("cp.async.commit_group;" ::: "memory");
}
__device__ __forceinline__ void cpa_wait1() {
    asm volatile("cp.async.wait_group 1;" ::: "memory");
}
__device__ __forceinline__ void cpa_wait0() {
    asm volatile("cp.async.wait_group 0;" ::: "memory");
}

// ---------------- smem layout ----------------
constexpr int STAGES = 3;
constexpr int KC = 64;          // k per chunk
constexpr int KPC = KC / 2;     // 32 k-pairs
constexpr int NCH = 512 / KC;   // 8 chunks total
constexpr int NTHREADS = 512;   // 16 warps
constexpr int GRID_P = 148;     // persistent grid (1 CTA/SM via smem)
__device__ __forceinline__ int a_off(int st, int kp, int row) {
    return st * (KPC * 128) + kp * 128 + (row ^ ((kp & 3) << 2));
}
__device__ __forceinline__ int b_off(int st, int kp, int col) {
    return STAGES * (KPC * 128) + st * (KPC * 128) + kp * 128 + (col ^ ((kp & 3) << 2));
}
constexpr int SMEM_BYTES = 2 * STAGES * KPC * 128 * 8;  // 192 KB

// fragment set for one k16 s-block, 32x32 warp tile
struct Frags {
    uint32_t ah[2][4], aml[2][4];
    uint32_t bh[4][2], bml[4][2];
};

// ======================= async bf16-split GEMM body =======================
// Computes C[bm:bm+128, bn:bn+128] partial over K chunks [ch0, ch0+nch)
// of C = A[M,512] @ B[512,Ncol] (+ bias if non-null).
// 512 threads, 16 warps in 4(m) x 4(n) grid, 32x32 warp tile.
// MODE 0: A from pre-split global Asp [kp][AS rows], row offset abase (cp.async)
// MODE 1: A row m = sum of 4 child h-rows (fp32 H) of node pbase+m (reg gather)
template <int MODE>
__device__ __forceinline__
void gemm_body(const uint2* __restrict__ Asp, int AS, int abase,
               const float* __restrict__ H, int pbase,
               const uint2* __restrict__ Bsp,
               const float* __restrict__ bias, float* __restrict__ C,
               int M, int Ncol, int bm, int bn, int ch0, int nch) {
    extern __shared__ uint2 sm2[];
    const uint32_t sbase = (uint32_t)__cvta_generic_to_shared(sm2);
    const int tid = threadIdx.x;
    const int wid = tid >> 5;
    const int lid = tid & 31;
    const int wm = (wid & 3) * 32;       // 4 m-tiles of 32
    const int wn = (wid >> 2) * 32;      // 4 n-tiles of 32
    const int g = lid >> 2;
    const int c3 = lid & 3;

    // staging assignments (512 threads)
    const int srow = tid & 127;          // A row
    const int skpb = (tid >> 7) * 8;     // A: 8 kp per thread
    const int scol = (tid & 63) * 2;     // B: col pair
    const int skp4 = (tid >> 6) * 4;     // B: 4 kp per thread

    auto issueStage = [&](int chg, int st) {   // chg = GLOBAL chunk index
        if (MODE == 0) {
#pragma unroll
            for (int i = 0; i < 8; ++i) {
                int kp = skpb + i;
                const uint2* src = Asp + (size_t)(chg * KPC + kp) * AS + abase + bm + srow;
                cpa8(sbase + (uint32_t)a_off(st, kp, srow) * 8, src);
            }
        } else {
            int gr = bm + srow;
            float v[16];
#pragma unroll
            for (int j = 0; j < 16; ++j) v[j] = 0.f;
            if (gr < M) {
                int p = pbase + gr;
                int kb = chg * KC + skpb * 2;
#pragma unroll
                for (int kk = 0; kk < 4; ++kk) {
                    int cid = child_id(p, kk);
                    const float* hp = H + (size_t)cid * 512 + kb;
#pragma unroll
                    for (int j = 0; j < 4; ++j) {
                        float4 t = *reinterpret_cast<const float4*>(hp + 4 * j);
                        v[4 * j + 0] += t.x; v[4 * j + 1] += t.y;
                        v[4 * j + 2] += t.z; v[4 * j + 3] += t.w;
                    }
                }
            }
#pragma unroll
            for (int i = 0; i < 8; ++i)
                sm2[a_off(st, skpb + i, srow)] = split_pack(v[2 * i], v[2 * i + 1]);
        }
#pragma unroll
        for (int i = 0; i < 4; ++i) {
            int kp = skp4 + i;
            const uint2* src = Bsp + (size_t)(chg * KPC + kp) * Ncol + bn + scol;
            cpa16(sbase + (uint32_t)b_off(st, kp, scol) * 8, src);
        }
    };

    float acc[2][4][4];
#pragma unroll
    for (int mt = 0; mt < 2; ++mt)
#pragma unroll
        for (int nt = 0; nt < 4; ++nt)
#pragma unroll
            for (int i = 0; i < 4; ++i) acc[mt][nt][i] = 0.f;

    auto loadFrag = [&](Frags& F, int st, int s) {
#pragma unroll
        for (int mt = 0; mt < 2; ++mt) {
            int r0 = wm + mt * 16 + g;
            uint2 t;
            t = sm2[a_off(st, s * 8 + c3, r0)];          F.ah[mt][0] = t.x; F.aml[mt][0] = t.y;
            t = sm2[a_off(st, s * 8 + c3, r0 + 8)];      F.ah[mt][1] = t.x; F.aml[mt][1] = t.y;
            t = sm2[a_off(st, s * 8 + c3 + 4, r0)];      F.ah[mt][2] = t.x; F.aml[mt][2] = t.y;
            t = sm2[a_off(st, s * 8 + c3 + 4, r0 + 8)];  F.ah[mt][3] = t.x; F.aml[mt][3] = t.y;
        }
#pragma unroll
        for (int nt = 0; nt < 4; ++nt) {
            int n0 = wn + nt * 8 + g;
            uint2 t;
            t = sm2[b_off(st, s * 8 + c3, n0)];      F.bh[nt][0] = t.x; F.bml[nt][0] = t.y;
            t = sm2[b_off(st, s * 8 + c3 + 4, n0)];  F.bh[nt][1] = t.x; F.bml[nt][1] = t.y;
        }
    };

    auto runMMA = [&](const Frags& F) {
#pragma unroll
        for (int mt = 0; mt < 2; ++mt)
#pragma unroll
            for (int nt = 0; nt < 4; ++nt)
                mma16(acc[mt][nt], F.ah[mt], F.bh[nt]);
#pragma unroll
        for (int mt = 0; mt < 2; ++mt)
#pragma unroll
            for (int nt = 0; nt < 4; ++nt)
                mma16(acc[mt][nt], F.ah[mt], F.bml[nt]);
#pragma unroll
        for (int mt = 0; mt < 2; ++mt)
#pragma unroll
            for (int nt = 0; nt < 4; ++nt)
                mma16(acc[mt][nt], F.aml[mt], F.bh[nt]);
    };

    // prologue: fill up to STAGES-1 stages (bounded by nch)
    const int pro = (nch < STAGES - 1) ? nch : (STAGES - 1);
    for (int s = 0; s < pro; ++s) {
        issueStage(ch0 + s, s);
        cpa_commit();
    }

    Frags F;
    for (int chl = 0; chl < nch; ++chl) {
        int issued = chl + STAGES - 1;
        if (issued > nch) issued = nch;
        if (issued - chl - 1 >= 1) cpa_wait1(); else cpa_wait0();
        __syncthreads();
        int nx = chl + STAGES - 1;
        if (nx < nch) {
            issueStage(ch0 + nx, nx % STAGES);
            cpa_commit();
        }
        const int st = chl % STAGES;
#pragma unroll
        for (int s = 0; s < 4; ++s) {
            loadFrag(F, st, s);
            runMMA(F);
        }
    }

    // epilogue
#pragma unroll
    for (int mt = 0; mt < 2; ++mt) {
        int r = bm + wm + mt * 16 + g;
        int r2 = r + 8;
#pragma unroll
        for (int nt = 0; nt < 4; ++nt) {
            int col = bn + wn + nt * 8 + 2 * c3;
            float b0 = bias ? bias[col] : 0.f;
            float b1 = bias ? bias[col + 1] : 0.f;
            if (r < M) {
                float2 o = make_float2(acc[mt][nt][0] + b0, acc[mt][nt][1] + b1);
                *reinterpret_cast<float2*>(&C[(size_t)r * Ncol + col]) = o;
            }
            if (r2 < M) {
                float2 o = make_float2(acc[mt][nt][2] + b0, acc[mt][nt][3] + b1);
                *reinterpret_cast<float2*>(&C[(size_t)r2 * Ncol + col]) = o;
            }
        }
    }
}

// plain single-GEMM kernel (used for ifou; full K)
template <int MODE>
__global__ __launch_bounds__(NTHREADS, 1)
void gemm_async(const uint2* __restrict__ Asp, int AS, int abase,
                const float* __restrict__ H, int pbase,
                const uint2* __restrict__ Bsp,
                const float* __restrict__ bias, float* __restrict__ C,
                int M, int Ncol) {
    gemm_body<MODE>(Asp, AS, abase, H, pbase, Bsp, bias, C, M, Ncol,
                    blockIdx.y * 128, blockIdx.x * 128, 0, NCH);
}

// ---------------- grid barrier (all CTAs co-resident: grid=148, 1 CTA/SM) ----------
__device__ __forceinline__ void grid_bar(unsigned target) {
    __syncthreads();
    if (threadIdx.x == 0) {
        __threadfence();
        unsigned t = atomicAdd(&g_bar_cnt, 1u);
        if (t == gridDim.x - 1) {
            g_bar_cnt = 0;
            __threadfence();
            atomicExch(&g_bar_gen, target);
        } else {
            volatile unsigned* vg = &g_bar_gen;
            while (*vg != target) { }
            __threadfence();
        }
    }
    __syncthreads();
}

// ---------------- level config ----------------
__device__ const int lv_base[6] = {3072, 3755, 4011, 4075, 4091, 4095};
__device__ const int lv_m[6]    = {683, 256, 64, 16, 4, 1};
__device__ const int lv_pb[6]   = {0, 3072, 3755, 4011, 4075, 4091};
__device__ const int lv_pc[6]   = {3072, 683, 256, 64, 16, 4};
__device__ const int lv_si[6]   = {2, 4, 4, 4, 4, 4};
__device__ const int lv_sf[6]   = {2, 4, 4, 4, 4, 4};

// ======================= fused persistent tail kernel =======================
// leaf pass -> [gemm(iou,fw) -> barrier -> combine -> barrier] x 6 levels -> out
__global__ __launch_bounds__(NTHREADS, 1)
void tree_tail(const float* __restrict__ ifou,
               const uint2* __restrict__ wss, const float* __restrict__ bs,
               float* __restrict__ ioup,
               const uint2* __restrict__ wfs, const float* __restrict__ bf,
               float* __restrict__ fwp,
               float* __restrict__ cbuf, float* __restrict__ hbuf,
               uint2* __restrict__ hsp, float* __restrict__ out) {
    const int j = threadIdx.x;
    unsigned bt = *(volatile unsigned*)&g_bar_gen;   // all threads read pre-launch value

    // ---- leaf pass (nodes 0..3071) ----
    for (int p = blockIdx.x; p < 3072; p += gridDim.x) {
        const float* r = ifou + (size_t)p * 2048;
        float iv = sigmoidf_(r[j] + bs[j]);
        float ov = sigmoidf_(r[1024 + j] + bs[512 + j]);
        float uv = tanhf(r[1536 + j] + bs[1024 + j]);
        float c = iv * uv;
        float h = ov * tanhf(c);
        cbuf[(size_t)p * MEM + j] = c;
        hbuf[(size_t)p * MEM + j] = h;
        float hn = __shfl_down_sync(0xffffffffu, h, 1);
        if ((j & 1) == 0) hsp[(size_t)(j >> 1) * HS + p] = split_pack(h, hn);
    }
    grid_bar(++bt);

    for (int l = 0; l < 6; ++l) {
        const int base = lv_base[l], m = lv_m[l];
        const int pb = lv_pb[l], pc = lv_pc[l];
        const int si = lv_si[l], sf = lv_sf[l];
        const int nyi = (m + 127) >> 7;
        const int nyf = (pc + 127) >> 7;
        const int NI = 12 * nyi * si;
        const int NF = 4 * nyf * sf;
        const int nchi = NCH / si, nchf = NCH / sf;

        // ---- GEMM jobs: [iou tiles x splitK][fw tiles x splitK] ----
        for (int job = blockIdx.x; job < NI + NF; job += gridDim.x) {
            __syncthreads();   // protect smem from previous job
            if (job < NI) {
                int sp = job % si, tile = job / si;
                int x = tile % 12, y = tile / 12;
                gemm_body<1>(nullptr, 0, 0, hbuf, base, wss,
                             sp == 0 ? bs : nullptr,
                             ioup + (size_t)sp * IOU_P, m, 1536,
                             y * 128, x * 128, sp * nchi, nchi);
            } else {
                int j2 = job - NI;
                int sp = j2 % sf, tile = j2 / sf;
                int x = tile % 4, y = tile / 4;
                gemm_body<0>(hsp, HS, pb, nullptr, 0, wfs,
                             sp == 0 ? bf : nullptr,
                             fwp + (size_t)sp * FW_P + (size_t)pb * MEM, pc, 512,
                             y * 128, x * 128, sp * nchf, nchf);
            }
        }
        grid_bar(++bt);

        // ---- combine (sums exactly si iou slices and sf fw slices) ----
        for (int mm = blockIdx.x; mm < m; mm += gridDim.x) {
            int p = base + mm;
            const float* r = ifou + (size_t)p * 2048;
            float ix = r[j], fx = r[512 + j], ox = r[1024 + j], ux = r[1536 + j];
            float i_s = 0.f, o_s = 0.f, u_s = 0.f;
            for (int sp = 0; sp < si; ++sp) {
                const float* ip = ioup + (size_t)sp * IOU_P + (size_t)mm * 1536 + j;
                i_s += ip[0]; o_s += ip[512]; u_s += ip[1024];
            }
            float iv = sigmoidf_(ix + i_s);
            float ov = sigmoidf_(ox + o_s);
            float uv = tanhf(ux + u_s);
            float c = iv * uv;
#pragma unroll
            for (int k = 0; k < 4; ++k) {
                int cid = child_id(p, k);
                size_t fo = (size_t)cid * MEM + j;
                float fraw = 0.f;
                for (int sp = 0; sp < sf; ++sp) fraw += fwp[(size_t)sp * FW_P + fo];
                c += sigmoidf_(fraw + fx) * cbuf[(size_t)cid * MEM + j];
            }
            float h = ov * tanhf(c);
            cbuf[(size_t)p * MEM + j] = c;
            hbuf[(size_t)p * MEM + j] = h;
            float hn = __shfl_down_sync(0xffffffffu, h, 1);
            if ((j & 1) == 0) hsp[(size_t)(j >> 1) * HS + p] = split_pack(h, hn);
            if (p == NN - 1) out[j] = h;
        }
        grid_bar(++bt);
    }
}

// ---------------- pre-split kernels ----------------
__global__ void split_w_all(const float* __restrict__ Wx, const float* __restrict__ Ws,
                            const float* __restrict__ Wf,
                            uint2* __restrict__ wxs, uint2* __restrict__ wss,
                            uint2* __restrict__ wfs) {
    int n = blockIdx.x * 256 + threadIdx.x;   // 0..4095
    int kp = blockIdx.y;                      // 0..255
    const float* W; uint2* out; int Ncol; int nn;
    if (n < 2048)      { W = Wx; out = wxs; Ncol = 2048; nn = n; }
    else if (n < 3584) { W = Ws; out = wss; Ncol = 1536; nn = n - 2048; }
    else               { W = Wf; out = wfs; Ncol = 512;  nn = n - 3584; }
    float a = W[(size_t)(2 * kp) * Ncol + nn];
    float b = W[(size_t)(2 * kp + 1) * Ncol + nn];
    out[(size_t)kp * Ncol + nn] = split_pack(a, b);
}

// inputs[4096][512] -> isp[kp][4096] (smem transpose)
__global__ void split_in_kernel(const float* __restrict__ in, uint2* __restrict__ out) {
    __shared__ float2 tile[32][33];
    int row = blockIdx.x * 32 + threadIdx.y;
    int kp = blockIdx.y * 32 + threadIdx.x;
    tile[threadIdx.y][threadIdx.x] = *reinterpret_cast<const float2*>(in + (size_t)row * 512 + 2 * kp);
    __syncthreads();
    int orow = blockIdx.x * 32 + threadIdx.x;
    int okp = blockIdx.y * 32 + threadIdx.y;
    float2 v = tile[threadIdx.x][threadIdx.y];
    out[(size_t)okp * 4096 + orow] = split_pack(v.x, v.y);
}

// ---------------- init ----------------
__global__ void init_kernel(float* cbuf, float* hbuf) {
    int j = threadIdx.x;
    cbuf[(size_t)NN * MEM + j] = 0.f;
    hbuf[(size_t)NN * MEM + j] = 0.f;
}

// ---------------- launch ----------------
extern "C" void kernel_launch(void* const* d_in, const int* in_sizes, int n_in,
                              void* d_out, int out_size) {
    const float* inputs = (const float*)d_in[0];
    const float* Wx     = (const float*)d_in[1];
    const float* bx     = (const float*)d_in[2];
    const float* Ws     = (const float*)d_in[3];
    const float* bs     = (const float*)d_in[4];
    const float* Wf     = (const float*)d_in[5];
    const float* bf     = (const float*)d_in[6];
    float* out = (float*)d_out;

    float *ifou, *cbuf, *hbuf, *iou, *fw;
    uint2 *wxs, *wss, *wfs, *isp, *hsp;
    cudaGetSymbolAddress((void**)&ifou, g_ifou);
    cudaGetSymbolAddress((void**)&cbuf, g_c);
    cudaGetSymbolAddress((void**)&hbuf, g_h);
    cudaGetSymbolAddress((void**)&iou, g_iou);
    cudaGetSymbolAddress((void**)&fw, g_fw);
    cudaGetSymbolAddress((void**)&wxs, g_wxs);
    cudaGetSymbolAddress((void**)&wss, g_wss);
    cudaGetSymbolAddress((void**)&wfs, g_wfs);
    cudaGetSymbolAddress((void**)&isp, g_isp);
    cudaGetSymbolAddress((void**)&hsp, g_hsp);

    cudaFuncSetAttribute(gemm_async<0>, cudaFuncAttributeMaxDynamicSharedMemorySize, SMEM_BYTES);
    cudaFuncSetAttribute(tree_tail, cudaFuncAttributeMaxDynamicSharedMemorySize, SMEM_BYTES);

    init_kernel<<<1, 512>>>(cbuf, hbuf);

    // pre-split constants
    split_w_all<<<dim3(16, 256), 256>>>(Wx, Ws, Wf, wxs, wss, wfs);
    split_in_kernel<<<dim3(4096 / 32, 256 / 32), dim3(32, 32)>>>(inputs, isp);

    // ifou = inputs @ Wx + bx  (full-K, throughput-bound)
    gemm_async<0><<<dim3(2048 / 128, 4096 / 128), NTHREADS, SMEM_BYTES>>>(
        isp, 4096, 0, nullptr, 0, wxs, bx, ifou, NN, 2048);

    // everything after ifou: one persistent kernel (leaf + 6 levels + output)
    tree_tail<<<GRID_P, NTHREADS, SMEM_BYTES>>>(
        ifou, wss, bs, iou, wfs, bf, fw, cbuf, hbuf, hsp, out);
}

// round 15
// speedup vs baseline: 1.3407x; 1.3407x over previous
#include <cuda_runtime.h>
#include <cuda_bf16.h>
#include <math.h>
#include <stdint.h>

#define NN 4096
#define MEM 512
#define HS 4224   // padded row count for h_split (level tiles read past last node)

constexpr int NSPLIT = 4;                     // max split-K factor for level GEMMs
constexpr size_t IOU_P = (size_t)683 * 1536;  // iou partial slice stride
constexpr size_t FW_P  = (size_t)(NN + 1) * MEM;  // fw partial slice stride

// ---------------- scratch (static device globals; no allocation) ----------------
__device__ float g_ifou[NN * 2048];
__device__ float g_c[(NN + 1) * MEM];
__device__ float g_h[(NN + 1) * MEM];
__device__ float g_iou[NSPLIT * 683 * 1536];        // split-K partials
__device__ float g_fw[NSPLIT * (NN + 1) * MEM];     // split-K partials (sentinel rows stay 0)
// pre-split (hi,mid) bf16x2 pairs, packed per k-pair
__device__ uint2 g_wxs[256 * 2048];   // Wx split [kp][n]
__device__ uint2 g_wss[256 * 1536];   // Ws split [kp][n]
__device__ uint2 g_wfs[256 * 512];    // Wf split [kp][n]
__device__ uint2 g_isp[256 * 4096];   // inputs split, transposed [kp][row]
__device__ uint2 g_hsp[256 * HS];     // h split, transposed [kp][node]

__device__ __forceinline__ float sigmoidf_(float x) { return 1.0f / (1.0f + expf(-x)); }

__device__ __forceinline__ int child_id(int p, int k) {
    int c = 4 * p - 12289 + k;
    return c < 0 ? NN : c;
}

// ---------------- bf16 split helpers ----------------
__device__ __forceinline__ uint2 split_pack(float x0, float x1) {
    __nv_bfloat162 h = __floats2bfloat162_rn(x0, x1);
    float r0 = x0 - __bfloat162float(h.x);
    float r1 = x1 - __bfloat162float(h.y);
    __nv_bfloat162 m = __floats2bfloat162_rn(r0, r1);
    uint2 o;
    o.x = *reinterpret_cast<uint32_t*>(&h);
    o.y = *reinterpret_cast<uint32_t*>(&m);
    return o;
}

__device__ __forceinline__ void mma16(float* d, const uint32_t* a, const uint32_t* b) {
    asm volatile(
        "mma.sync.aligned.m16n8k16.row.col.f32.bf16.bf16.f32 "
        "{%0,%1,%2,%3}, {%4,%5,%6,%7}, {%8,%9}, {%0,%1,%2,%3};"
        : "+f"(d[0]), "+f"(d[1]), "+f"(d[2]), "+f"(d[3])
        : "r"(a[0]), "r"(a[1]), "r"(a[2]), "r"(a[3]), "r"(b[0]), "r"(b[1]));
}

__device__ __forceinline__ void cpa8(uint32_t dst, const void* src) {
    asm volatile("cp.async.ca.shared.global [%0], [%1], 8;" :: "r"(dst), "l"(src));
}
__device__ __forceinline__ void cpa16(uint32_t dst, const void* src) {
    asm volatile("cp.async.cg.shared.global [%0], [%1], 16;" :: "r"(dst), "l"(src));
}
__device__ __forceinline__ void cpa_commit() {
    asm volatile("cp.async.commit_group;" ::: "memory");
}
__device__ __forceinline__ void cpa_wait1() {
    asm volatile("cp.async.wait_group 1;" ::: "memory");
}
__device__ __forceinline__ void cpa_wait0() {
    asm volatile("cp.async.wait_group 0;" ::: "memory");
}

// ---------------- smem layout ----------------
constexpr int STAGES = 3;
constexpr int KC = 64;          // k per chunk
constexpr int KPC = KC / 2;     // 32 k-pairs
constexpr int NCH = 512 / KC;   // 8 chunks total
constexpr int NTHREADS = 512;   // 16 warps
__device__ __forceinline__ int a_off(int st, int kp, int row) {
    return st * (KPC * 128) + kp * 128 + (row ^ ((kp & 3) << 2));
}
__device__ __forceinline__ int b_off(int st, int kp, int col) {
    return STAGES * (KPC * 128) + st * (KPC * 128) + kp * 128 + (col ^ ((kp & 3) << 2));
}
constexpr int SMEM_BYTES = 2 * STAGES * KPC * 128 * 8;  // 192 KB

// fragment set for one k16 s-block, 32x32 warp tile
struct Frags {
    uint32_t ah[2][4], aml[2][4];
    uint32_t bh[4][2], bml[4][2];
};

// ======================= async bf16-split GEMM body =======================
// Computes C[bm:bm+128, bn:bn+128] partial over K chunks [ch0, ch0+nch)
// of C = A[M,512] @ B[512,Ncol] (+ bias if non-null).
// 512 threads, 16 warps in 4(m) x 4(n) grid, 32x32 warp tile.
// MODE 0: A from pre-split global Asp [kp][AS rows], row offset abase (cp.async)
// MODE 1: A row m = sum of 4 child h-rows (fp32 H) of node pbase+m (reg gather)
template <int MODE>
__device__ __forceinline__
void gemm_body(const uint2* __restrict__ Asp, int AS, int abase,
               const float* __restrict__ H, int pbase,
               const uint2* __restrict__ Bsp,
               const float* __restrict__ bias, float* __restrict__ C,
               int M, int Ncol, int bm, int bn, int ch0, int nch) {
    extern __shared__ uint2 sm2[];
    const uint32_t sbase = (uint32_t)__cvta_generic_to_shared(sm2);
    const int tid = threadIdx.x;
    const int wid = tid >> 5;
    const int lid = tid & 31;
    const int wm = (wid & 3) * 32;       // 4 m-tiles of 32
    const int wn = (wid >> 2) * 32;      // 4 n-tiles of 32
    const int g = lid >> 2;
    const int c3 = lid & 3;

    // staging assignments (512 threads)
    const int srow = tid & 127;          // A row
    const int skpb = (tid >> 7) * 8;     // A: 8 kp per thread
    const int scol = (tid & 63) * 2;     // B: col pair
    const int skp4 = (tid >> 6) * 4;     // B: 4 kp per thread

    auto issueStage = [&](int chg, int st) {   // chg = GLOBAL chunk index
        if (MODE == 0) {
#pragma unroll
            for (int i = 0; i < 8; ++i) {
                int kp = skpb + i;
                const uint2* src = Asp + (size_t)(chg * KPC + kp) * AS + abase + bm + srow;
                cpa8(sbase + (uint32_t)a_off(st, kp, srow) * 8, src);
            }
        } else {
            int gr = bm + srow;
            float v[16];
#pragma unroll
            for (int j = 0; j < 16; ++j) v[j] = 0.f;
            if (gr < M) {
                int p = pbase + gr;
                int kb = chg * KC + skpb * 2;
#pragma unroll
                for (int kk = 0; kk < 4; ++kk) {
                    int cid = child_id(p, kk);
                    const float* hp = H + (size_t)cid * 512 + kb;
#pragma unroll
                    for (int j = 0; j < 4; ++j) {
                        float4 t = *reinterpret_cast<const float4*>(hp + 4 * j);
                        v[4 * j + 0] += t.x; v[4 * j + 1] += t.y;
                        v[4 * j + 2] += t.z; v[4 * j + 3] += t.w;
                    }
                }
            }
#pragma unroll
            for (int i = 0; i < 8; ++i)
                sm2[a_off(st, skpb + i, srow)] = split_pack(v[2 * i], v[2 * i + 1]);
        }
#pragma unroll
        for (int i = 0; i < 4; ++i) {
            int kp = skp4 + i;
            const uint2* src = Bsp + (size_t)(chg * KPC + kp) * Ncol + bn + scol;
            cpa16(sbase + (uint32_t)b_off(st, kp, scol) * 8, src);
        }
    };

    float acc[2][4][4];
#pragma unroll
    for (int mt = 0; mt < 2; ++mt)
#pragma unroll
        for (int nt = 0; nt < 4; ++nt)
#pragma unroll
            for (int i = 0; i < 4; ++i) acc[mt][nt][i] = 0.f;

    auto loadFrag = [&](Frags& F, int st, int s) {
#pragma unroll
        for (int mt = 0; mt < 2; ++mt) {
            int r0 = wm + mt * 16 + g;
            uint2 t;
            t = sm2[a_off(st, s * 8 + c3, r0)];          F.ah[mt][0] = t.x; F.aml[mt][0] = t.y;
            t = sm2[a_off(st, s * 8 + c3, r0 + 8)];      F.ah[mt][1] = t.x; F.aml[mt][1] = t.y;
            t = sm2[a_off(st, s * 8 + c3 + 4, r0)];      F.ah[mt][2] = t.x; F.aml[mt][2] = t.y;
            t = sm2[a_off(st, s * 8 + c3 + 4, r0 + 8)];  F.ah[mt][3] = t.x; F.aml[mt][3] = t.y;
        }
#pragma unroll
        for (int nt = 0; nt < 4; ++nt) {
            int n0 = wn + nt * 8 + g;
            uint2 t;
            t = sm2[b_off(st, s * 8 + c3, n0)];      F.bh[nt][0] = t.x; F.bml[nt][0] = t.y;
            t = sm2[b_off(st, s * 8 + c3 + 4, n0)];  F.bh[nt][1] = t.x; F.bml[nt][1] = t.y;
        }
    };

    auto runMMA = [&](const Frags& F) {
#pragma unroll
        for (int mt = 0; mt < 2; ++mt)
#pragma unroll
            for (int nt = 0; nt < 4; ++nt)
                mma16(acc[mt][nt], F.ah[mt], F.bh[nt]);
#pragma unroll
        for (int mt = 0; mt < 2; ++mt)
#pragma unroll
            for (int nt = 0; nt < 4; ++nt)
                mma16(acc[mt][nt], F.ah[mt], F.bml[nt]);
#pragma unroll
        for (int mt = 0; mt < 2; ++mt)
#pragma unroll
            for (int nt = 0; nt < 4; ++nt)
                mma16(acc[mt][nt], F.aml[mt], F.bh[nt]);
    };

    // prologue: fill up to STAGES-1 stages (bounded by nch)
    const int pro = (nch < STAGES - 1) ? nch : (STAGES - 1);
    for (int s = 0; s < pro; ++s) {
        issueStage(ch0 + s, s);
        cpa_commit();
    }

    Frags F;
    for (int chl = 0; chl < nch; ++chl) {
        int issued = chl + STAGES - 1;
        if (issued > nch) issued = nch;
        if (issued - chl - 1 >= 1) cpa_wait1(); else cpa_wait0();
        __syncthreads();
        int nx = chl + STAGES - 1;
        if (nx < nch) {
            issueStage(ch0 + nx, nx % STAGES);
            cpa_commit();
        }
        const int st = chl % STAGES;
#pragma unroll
        for (int s = 0; s < 4; ++s) {
            loadFrag(F, st, s);
            runMMA(F);
        }
    }

    // epilogue
#pragma unroll
    for (int mt = 0; mt < 2; ++mt) {
        int r = bm + wm + mt * 16 + g;
        int r2 = r + 8;
#pragma unroll
        for (int nt = 0; nt < 4; ++nt) {
            int col = bn + wn + nt * 8 + 2 * c3;
            float b0 = bias ? bias[col] : 0.f;
            float b1 = bias ? bias[col + 1] : 0.f;
            if (r < M) {
                float2 o = make_float2(acc[mt][nt][0] + b0, acc[mt][nt][1] + b1);
                *reinterpret_cast<float2*>(&C[(size_t)r * Ncol + col]) = o;
            }
            if (r2 < M) {
                float2 o = make_float2(acc[mt][nt][2] + b0, acc[mt][nt][3] + b1);
                *reinterpret_cast<float2*>(&C[(size_t)r2 * Ncol + col]) = o;
            }
        }
    }
}

// ifou for LEAF rows only, skipping the unused f-gate column tiles.
// grid = (12, 24): x -> column tile in {0..3 (i), 8..15 (o,u)}, y -> 128-row tile
__global__ __launch_bounds__(NTHREADS, 1)
void gemm_ifou_leaf(const uint2* __restrict__ isp, const uint2* __restrict__ wxs,
                    const float* __restrict__ bx, float* __restrict__ ifou) {
    int x = blockIdx.x;
    int bn = ((x < 4) ? x : x + 4) * 128;
    gemm_body<0>(isp, 4096, 0, nullptr, 0, wxs, bx, ifou, 3072, 2048,
                 blockIdx.y * 128, bn, 0, NCH);
}

// Level-0 merged launch: 464 flat jobs
//   [0,128)   : ifou for internal rows 3072..4095 (full K, 16x8 tiles)
//   [128,272) : iou L0 (683 rows), split-K 2, 12x6 tiles
//   [272,464) : fw for leaves (3072 rows), split-K 2, 4x24 tiles
__global__ __launch_bounds__(NTHREADS, 1)
void gemm_l0(const uint2* __restrict__ isp, const uint2* __restrict__ wxs,
             const float* __restrict__ bx, float* __restrict__ ifou,
             const float* __restrict__ hbuf,
             const uint2* __restrict__ wss, const float* __restrict__ bs,
             float* __restrict__ ioup,
             const uint2* __restrict__ hsp,
             const uint2* __restrict__ wfs, const float* __restrict__ bf,
             float* __restrict__ fwp) {
    int job = blockIdx.x;
    if (job < 128) {
        int x = job & 15, y = job >> 4;
        gemm_body<0>(isp, 4096, 3072, nullptr, 0, wxs, bx,
                     ifou + (size_t)3072 * 2048, 1024, 2048,
                     y * 128, x * 128, 0, NCH);
    } else if (job < 272) {
        int jj = job - 128;
        int sp = jj & 1, tile = jj >> 1;
        int x = tile % 12, y = tile / 12;
        gemm_body<1>(nullptr, 0, 0, hbuf, 3072, wss,
                     sp == 0 ? bs : nullptr,
                     ioup + (size_t)sp * IOU_P, 683, 1536,
                     y * 128, x * 128, sp * 4, 4);
    } else {
        int jj = job - 272;
        int sp = jj & 1, tile = jj >> 1;
        int x = tile & 3, y = tile >> 2;
        gemm_body<0>(hsp, HS, 0, nullptr, 0, wfs,
                     sp == 0 ? bf : nullptr,
                     fwp + (size_t)sp * FW_P, 3072, 512,
                     y * 128, x * 128, sp * 4, 4);
    }
}

// dual split-K kernel for levels 1..5: z = split + 4*sel
__global__ __launch_bounds__(NTHREADS, 1)
void gemm_dual(const float* __restrict__ H, int pbase,
               const uint2* __restrict__ wss, const float* __restrict__ bs,
               float* __restrict__ ioup, int M1,
               const uint2* __restrict__ hsp, int abase,
               const uint2* __restrict__ wfs, const float* __restrict__ bf,
               float* __restrict__ fwp, int M0) {
    const int split = blockIdx.z & 3;
    const int ch0 = split * (NCH / NSPLIT);
    if (blockIdx.z < 4) {
        if ((int)blockIdx.x >= 12 || (int)(blockIdx.y * 128) >= M1) return;
        gemm_body<1>(nullptr, 0, 0, H, pbase, wss,
                     split == 0 ? bs : nullptr,
                     ioup + (size_t)split * IOU_P, M1, 1536,
                     blockIdx.y * 128, blockIdx.x * 128, ch0, NCH / NSPLIT);
    } else {
        if ((int)blockIdx.x >= 4 || (int)(blockIdx.y * 128) >= M0) return;
        gemm_body<0>(hsp, HS, abase, nullptr, 0, wfs,
                     split == 0 ? bf : nullptr,
                     fwp + (size_t)split * FW_P, M0, 512,
                     blockIdx.y * 128, blockIdx.x * 128, ch0, NCH / NSPLIT);
    }
}

// ---------------- pre-split kernels ----------------
__global__ void split_w_all(const float* __restrict__ Wx, const float* __restrict__ Ws,
                            const float* __restrict__ Wf,
                            uint2* __restrict__ wxs, uint2* __restrict__ wss,
                            uint2* __restrict__ wfs) {
    int n = blockIdx.x * 256 + threadIdx.x;   // 0..4095
    int kp = blockIdx.y;                      // 0..255
    const float* W; uint2* out; int Ncol; int nn;
    if (n < 2048)      { W = Wx; out = wxs; Ncol = 2048; nn = n; }
    else if (n < 3584) { W = Ws; out = wss; Ncol = 1536; nn = n - 2048; }
    else               { W = Wf; out = wfs; Ncol = 512;  nn = n - 3584; }
    float a = W[(size_t)(2 * kp) * Ncol + nn];
    float b = W[(size_t)(2 * kp + 1) * Ncol + nn];
    out[(size_t)kp * Ncol + nn] = split_pack(a, b);
}

// inputs[4096][512] -> isp[kp][4096] (smem transpose)
__global__ void split_in_kernel(const float* __restrict__ in, uint2* __restrict__ out) {
    __shared__ float2 tile[32][33];
    int row = blockIdx.x * 32 + threadIdx.y;
    int kp = blockIdx.y * 32 + threadIdx.x;
    tile[threadIdx.y][threadIdx.x] = *reinterpret_cast<const float2*>(in + (size_t)row * 512 + 2 * kp);
    __syncthreads();
    int orow = blockIdx.x * 32 + threadIdx.x;
    int okp = blockIdx.y * 32 + threadIdx.y;
    float2 v = tile[threadIdx.x][threadIdx.y];
    out[(size_t)okp * 4096 + orow] = split_pack(v.x, v.y);
}

// ---------------- elementwise kernels ----------------
__global__ void init_kernel(float* cbuf, float* hbuf) {
    int j = threadIdx.x;
    cbuf[(size_t)NN * MEM + j] = 0.f;
    hbuf[(size_t)NN * MEM + j] = 0.f;
}

__global__ void leaf_kernel(const float* __restrict__ ifou, const float* __restrict__ bs,
                            float* __restrict__ cbuf, float* __restrict__ hbuf,
                            uint2* __restrict__ hsp) {
    int p = blockIdx.x;
    int j = threadIdx.x;
    const float* r = ifou + (size_t)p * 2048;
    float iv = sigmoidf_(r[j] + bs[j]);
    float ov = sigmoidf_(r[1024 + j] + bs[512 + j]);
    float uv = tanhf(r[1536 + j] + bs[1024 + j]);
    float c = iv * uv;
    float h = ov * tanhf(c);
    cbuf[(size_t)p * MEM + j] = c;
    hbuf[(size_t)p * MEM + j] = h;
    float hn = __shfl_down_sync(0xffffffffu, h, 1);
    if ((j & 1) == 0) hsp[(size_t)(j >> 1) * HS + p] = split_pack(h, hn);
}

// combine: sums si iou slices and sf fw slices (fixed order, deterministic);
// root node also writes the kernel output.
__global__ void combine_kernel(const float* __restrict__ ifou, const float* __restrict__ ioup,
                               const float* __restrict__ fwp, float* __restrict__ cbuf,
                               float* __restrict__ hbuf, uint2* __restrict__ hsp,
                               int base, int si, int sf, float* __restrict__ out) {
    int m = blockIdx.x;
    int j = threadIdx.x;
    int p = base + m;
    const float* r = ifou + (size_t)p * 2048;
    float ix = r[j], fx = r[512 + j], ox = r[1024 + j], ux = r[1536 + j];
    float i_s = 0.f, o_s = 0.f, u_s = 0.f;
    for (int sp = 0; sp < si; ++sp) {
        const float* ip = ioup + (size_t)sp * IOU_P + (size_t)m * 1536 + j;
        i_s += ip[0]; o_s += ip[512]; u_s += ip[1024];
    }
    float iv = sigmoidf_(ix + i_s);
    float ov = sigmoidf_(ox + o_s);
    float uv = tanhf(ux + u_s);
    float c = iv * uv;
#pragma unroll
    for (int k = 0; k < 4; ++k) {
        int cid = child_id(p, k);
        size_t fo = (size_t)cid * MEM + j;
        float fraw = 0.f;
        for (int sp = 0; sp < sf; ++sp) fraw += fwp[(size_t)sp * FW_P + fo];
        c += sigmoidf_(fraw + fx) * cbuf[(size_t)cid * MEM + j];
    }
    float h = ov * tanhf(c);
    cbuf[(size_t)p * MEM + j] = c;
    hbuf[(size_t)p * MEM + j] = h;
    float hn = __shfl_down_sync(0xffffffffu, h, 1);
    if ((j & 1) == 0) hsp[(size_t)(j >> 1) * HS + p] = split_pack(h, hn);
    if (p == NN - 1) out[j] = h;
}

// ---------------- launch ----------------
extern "C" void kernel_launch(void* const* d_in, const int* in_sizes, int n_in,
                              void* d_out, int out_size) {
    const float* inputs = (const float*)d_in[0];
    const float* Wx     = (const float*)d_in[1];
    const float* bx     = (const float*)d_in[2];
    const float* Ws     = (const float*)d_in[3];
    const float* bs     = (const float*)d_in[4];
    const float* Wf     = (const float*)d_in[5];
    const float* bf     = (const float*)d_in[6];
    float* out = (float*)d_out;

    float *ifou, *cbuf, *hbuf, *iou, *fw;
    uint2 *wxs, *wss, *wfs, *isp, *hsp;
    cudaGetSymbolAddress((void**)&ifou, g_ifou);
    cudaGetSymbolAddress((void**)&cbuf, g_c);
    cudaGetSymbolAddress((void**)&hbuf, g_h);
    cudaGetSymbolAddress((void**)&iou, g_iou);
    cudaGetSymbolAddress((void**)&fw, g_fw);
    cudaGetSymbolAddress((void**)&wxs, g_wxs);
    cudaGetSymbolAddress((void**)&wss, g_wss);
    cudaGetSymbolAddress((void**)&wfs, g_wfs);
    cudaGetSymbolAddress((void**)&isp, g_isp);
    cudaGetSymbolAddress((void**)&hsp, g_hsp);

    cudaFuncSetAttribute(gemm_ifou_leaf, cudaFuncAttributeMaxDynamicSharedMemorySize, SMEM_BYTES);
    cudaFuncSetAttribute(gemm_l0, cudaFuncAttributeMaxDynamicSharedMemorySize, SMEM_BYTES);
    cudaFuncSetAttribute(gemm_dual, cudaFuncAttributeMaxDynamicSharedMemorySize, SMEM_BYTES);

    init_kernel<<<1, 512>>>(cbuf, hbuf);

    // pre-split constants
    split_w_all<<<dim3(16, 256), 256>>>(Wx, Ws, Wf, wxs, wss, wfs);
    split_in_kernel<<<dim3(4096 / 32, 256 / 32), dim3(32, 32)>>>(inputs, isp);

    // ifou for leaf rows only (i/o/u columns; f-gate tiles skipped)
    gemm_ifou_leaf<<<dim3(12, 24), NTHREADS, SMEM_BYTES>>>(isp, wxs, bx, ifou);

    leaf_kernel<<<3072, 512>>>(ifou, bs, cbuf, hbuf, hsp);

    // level 0 merged: ifou internal rows + iou L0 (split 2) + fw leaves (split 2)
    gemm_l0<<<464, NTHREADS, SMEM_BYTES>>>(isp, wxs, bx, ifou, hbuf,
                                           wss, bs, iou, hsp, wfs, bf, fw);
    combine_kernel<<<683, 512>>>(ifou, iou, fw, cbuf, hbuf, hsp, 3072, 2, 2, out);

    static const int baseArr[5] = {3755, 4011, 4075, 4091, 4095};
    static const int cntArr[5]  = {256, 64, 16, 4, 1};
    int prevBase = 3072, prevCnt = 683;
    for (int l = 0; l < 5; ++l) {
        int m = cntArr[l], base = baseArr[l];
        int gy = (m + 127) / 128;
        int gy0 = (prevCnt + 127) / 128;
        int gymax = gy > gy0 ? gy : gy0;
        gemm_dual<<<dim3(12, gymax, 2 * NSPLIT), NTHREADS, SMEM_BYTES>>>(
            hbuf, base, wss, bs, iou, m,
            hsp, prevBase, wfs, bf, fw + (size_t)prevBase * MEM, prevCnt);
        combine_kernel<<<m, 512>>>(ifou, iou, fw, cbuf, hbuf, hsp, base,
                                   NSPLIT, NSPLIT, out);
        prevBase = base;
        prevCnt = m;
    }
}